// round 5
// baseline (speedup 1.0000x reference)
#include <cuda_runtime.h>
#include <math.h>

#define BATCH   4
#define TQ      2048
#define TK      2048
#define DMODEL  1024
#define NHEADS  16
#define HDIM    64
#define MROWS   (BATCH * TQ)   // 8192

// ---------------- scratch (__device__ globals; no allocation allowed) -------
__device__ float g_Q[MROWS * DMODEL];   // (b,h,t,hd-paired)  tf32 bits, prescaled
__device__ float g_K[MROWS * DMODEL];   // (b,h,t,hd-paired)  tf32 bits
__device__ float g_V[MROWS * DMODEL];   // (b,h,hd,t-paired)  tf32 bits (V^T)
__device__ float g_O[MROWS * DMODEL];   // (b,t,dmodel) tf32 bits (unpaired)
__device__ float g_Xq[MROWS * DMODEL];  // x_q  tf32 bits, k-paired
__device__ float g_Xkv[MROWS * DMODEL]; // x_kv tf32 bits, k-paired
__device__ float g_Wq[DMODEL * DMODEL]; // tf32 bits, k-paired
__device__ float g_Wk[DMODEL * DMODEL];
__device__ float g_Wv[DMODEL * DMODEL];
__device__ float g_Wo[DMODEL * DMODEL]; // tf32 bits, unpaired

// ---------------- helpers ----------------------------------------------------
__device__ __forceinline__ unsigned f2tf(float x) {
    unsigned r;
    asm("cvt.rna.tf32.f32 %0, %1;" : "=r"(r) : "f"(x));
    return r;
}

__device__ __forceinline__ void mma_tf32(float* d, const unsigned* a, const unsigned* b) {
    asm volatile(
        "mma.sync.aligned.m16n8k8.row.col.f32.tf32.tf32.f32 "
        "{%0,%1,%2,%3}, {%4,%5,%6,%7}, {%8,%9}, {%0,%1,%2,%3};"
        : "+f"(d[0]), "+f"(d[1]), "+f"(d[2]), "+f"(d[3])
        : "r"(a[0]), "r"(a[1]), "r"(a[2]), "r"(a[3]), "r"(b[0]), "r"(b[1]));
}

__device__ __forceinline__ void cp16(void* smem_dst, const void* gmem_src) {
    unsigned s = (unsigned)__cvta_generic_to_shared(smem_dst);
    asm volatile("cp.async.cg.shared.global [%0], [%1], 16;" :: "r"(s), "l"(gmem_src));
}

// pair position within 8-block: k<4 -> 2k ; k>=4 -> 2(k-4)+1
__device__ __forceinline__ int ppos(int j) { return (j < 4) ? 2 * j : 2 * (j - 4) + 1; }

// ---------------- pre-convert passes -----------------------------------------
__global__ void cvt_pair_kernel(const float* __restrict__ src, float* __restrict__ dst, int n) {
    int i4 = (blockIdx.x * blockDim.x + threadIdx.x) * 4;
    if (i4 >= n) return;
    float4 v = *(const float4*)&src[i4];
    int base = i4 & ~7;
    int j = i4 & 7;              // 0 or 4
#pragma unroll
    for (int e = 0; e < 4; e++) {
        float x = (e == 0) ? v.x : (e == 1) ? v.y : (e == 2) ? v.z : v.w;
        dst[base + ppos(j + e)] = __uint_as_float(f2tf(x));
    }
}

__global__ void cvt_plain_kernel(const float* __restrict__ src, float* __restrict__ dst, int n) {
    int i4 = (blockIdx.x * blockDim.x + threadIdx.x) * 4;
    if (i4 >= n) return;
    float4 v = *(const float4*)&src[i4];
    v.x = __uint_as_float(f2tf(v.x));
    v.y = __uint_as_float(f2tf(v.y));
    v.z = __uint_as_float(f2tf(v.z));
    v.w = __uint_as_float(f2tf(v.w));
    *(float4*)&dst[i4] = v;
}

// ---------------- tf32 GEMM: C = A(M,K) @ W(N,K)^T ----------------------------
// 128x128x32 block, 256 threads, 8 warps of 64x32, cp.async double buffer.
// Inputs are pre-rounded tf32 bits. PAIRED -> k-paired layout, LDS.64 frags.
// MODE 0: plain fp32 row-major out. MODE 1: split-heads hd-paired tf32 (*scale).
// MODE 2: V^T layout (b,h,hd,t-paired) tf32.
#define BM   128
#define BN   128
#define BK   32
#define SSTR 40    // 40 % 32 == 8 -> conflict-free LDS.64 fragments

template <int MODE, bool PAIRED>
__global__ void __launch_bounds__(256, 2)
gemm_tf32(const float* __restrict__ A, const float* __restrict__ W,
          float* __restrict__ C, float scale)
{
    extern __shared__ float sm[];
    float* As = sm;                       // [2][BM][SSTR]
    float* Ws = sm + 2 * BM * SSTR;       // [2][BN][SSTR]

    const int tid  = threadIdx.x;
    const int lane = tid & 31;
    const int warp = tid >> 5;
    const int wm   = warp >> 2;
    const int wn   = warp & 3;
    const int bm   = blockIdx.y * BM;
    const int bn   = blockIdx.x * BN;
    const int lr   = lane >> 2;
    const int lc   = lane & 3;

    float acc[4][4][4];
#pragma unroll
    for (int i = 0; i < 4; i++)
#pragma unroll
        for (int j = 0; j < 4; j++)
#pragma unroll
            for (int c = 0; c < 4; c++) acc[i][j][c] = 0.f;

    const int NIT = DMODEL / BK;

    auto load_stage = [&](int st, int k0) {
#pragma unroll
        for (int r = 0; r < 4; r++) {
            int id = tid + r * 256;
            int m  = id >> 3;
            int k4 = (id & 7) * 4;
            cp16(&As[(st * BM + m) * SSTR + k4], &A[(size_t)(bm + m) * DMODEL + k0 + k4]);
            cp16(&Ws[(st * BN + m) * SSTR + k4], &W[(size_t)(bn + m) * DMODEL + k0 + k4]);
        }
        asm volatile("cp.async.commit_group;");
    };

    load_stage(0, 0);

    for (int it = 0; it < NIT; it++) {
        if (it + 1 < NIT) {
            load_stage((it + 1) & 1, (it + 1) * BK);
            asm volatile("cp.async.wait_group 1;");
        } else {
            asm volatile("cp.async.wait_group 0;");
        }
        __syncthreads();
        const float* Ab = &As[(it & 1) * BM * SSTR];
        const float* Wb = &Ws[(it & 1) * BN * SSTR];

#pragma unroll
        for (int kk = 0; kk < 4; kk++) {
            const int k = kk * 8;
            unsigned af[4][4], bf[4][2];
#pragma unroll
            for (int mf = 0; mf < 4; mf++) {
                const int row = wm * 64 + mf * 16 + lr;
                if (PAIRED) {
                    float2 a0 = *(const float2*)&Ab[row * SSTR + k + 2 * lc];
                    float2 a1 = *(const float2*)&Ab[(row + 8) * SSTR + k + 2 * lc];
                    af[mf][0] = __float_as_uint(a0.x);
                    af[mf][1] = __float_as_uint(a1.x);
                    af[mf][2] = __float_as_uint(a0.y);
                    af[mf][3] = __float_as_uint(a1.y);
                } else {
                    const float* p = &Ab[row * SSTR + k + lc];
                    af[mf][0] = __float_as_uint(p[0]);
                    af[mf][1] = __float_as_uint(p[8 * SSTR]);
                    af[mf][2] = __float_as_uint(p[4]);
                    af[mf][3] = __float_as_uint(p[8 * SSTR + 4]);
                }
            }
#pragma unroll
            for (int nf = 0; nf < 4; nf++) {
                const int row = wn * 32 + nf * 8 + lr;
                if (PAIRED) {
                    float2 b0 = *(const float2*)&Wb[row * SSTR + k + 2 * lc];
                    bf[nf][0] = __float_as_uint(b0.x);
                    bf[nf][1] = __float_as_uint(b0.y);
                } else {
                    const float* p = &Wb[row * SSTR + k + lc];
                    bf[nf][0] = __float_as_uint(p[0]);
                    bf[nf][1] = __float_as_uint(p[4]);
                }
            }
#pragma unroll
            for (int mf = 0; mf < 4; mf++)
#pragma unroll
                for (int nf = 0; nf < 4; nf++)
                    mma_tf32(acc[mf][nf], af[mf], bf[nf]);
        }
        __syncthreads();
    }

    // epilogue
#pragma unroll
    for (int mf = 0; mf < 4; mf++) {
#pragma unroll
        for (int half = 0; half < 2; half++) {
            const int m = bm + wm * 64 + mf * 16 + lr + half * 8;
#pragma unroll
            for (int nf = 0; nf < 4; nf++) {
                const int n0 = bn + wn * 32 + nf * 8;
                float c0 = acc[mf][nf][half * 2], c1 = acc[mf][nf][half * 2 + 1];
                if (MODE == 0) {
                    *(float2*)&C[(size_t)m * DMODEL + n0 + 2 * lc] = make_float2(c0, c1);
                } else if (MODE == 1) {
                    // split heads, hd-paired, tf32, scaled
                    const int b = m >> 11, t = m & 2047;
                    const int pos0 = (lc < 2) ? 4 * lc : 4 * lc - 7;
                    const int pos1 = (lc < 2) ? 4 * lc + 2 : 4 * lc - 5;
                    const int na = n0 + pos0, nb = n0 + pos1;
                    float* base = &C[(((size_t)(b * NHEADS + (n0 >> 6)) * TQ + t) << 6)];
                    base[na & 63] = __uint_as_float(f2tf(c0 * scale));
                    base[nb & 63] = __uint_as_float(f2tf(c1 * scale));
                } else {
                    // V^T: (b,h,hd,t-paired)
                    const int b = m >> 11, t = m & 2047;
                    const int tp = (t & ~7) | ppos(lr);
                    const int n  = n0 + 2 * lc;
                    const int h  = n >> 6;
                    float* base = &C[(((size_t)(b * NHEADS + h) * HDIM)) * (size_t)TK];
                    base[(size_t)(n & 63) * TK + tp]       = __uint_as_float(f2tf(c0));
                    base[(size_t)((n + 1) & 63) * TK + tp] = __uint_as_float(f2tf(c1));
                }
            }
        }
    }
}

// ---------------- fused attention --------------------------------------------
// AQ=128 q-rows, 4 warps x 32 rows (2 m-tiles). Q resident in smem (paired hd),
// K double-buffered (paired hd), V^T single-buffered (paired t). P assembled via
// intra-quad shuffles (never hits smem). All operands tf32 bits, LDS.64 frags.
#define AQ   128
#define KT   64
#define STR  72   // 72 % 32 == 8 -> conflict-free LDS.64

__global__ void __launch_bounds__(128, 2)
attn_tf32(const float* __restrict__ Q, const float* __restrict__ K,
          const float* __restrict__ V, const float* __restrict__ mask,
          const unsigned char* __restrict__ kpm, float* __restrict__ O)
{
    extern __shared__ float sm[];
    float* Qs = sm;                      // 128 x 72 (resident)
    float* Ks = sm + AQ * STR;           // [2][64][72]
    float* Vs = Ks + 2 * KT * STR;       // 64 x 72 (V^T tile: rows=hd, cols=t-paired)

    const int tid  = threadIdx.x;
    const int lane = tid & 31;
    const int warp = tid >> 5;
    const int lr   = lane >> 2;
    const int lc   = lane & 3;

    const int q0 = blockIdx.x * AQ;
    const int bh = blockIdx.y;
    const int b  = bh >> 4;
    const int h  = bh & 15;

    const float* Qb = Q + (size_t)bh * TQ * HDIM;
    const float* Kb = K + (size_t)bh * TK * HDIM;
    const float* Vb = V + (size_t)bh * HDIM * TK;   // V^T rows=hd

    // stage Q tile (resident)
#pragma unroll
    for (int r = 0; r < 16; r++) {
        int id = tid + r * 128;          // 2048 slots: 128 rows x 16 float4
        int row = id >> 4, c4 = (id & 15) * 4;
        cp16(&Qs[row * STR + c4], &Qb[(size_t)(q0 + row) * HDIM + c4]);
    }
    asm volatile("cp.async.commit_group;");

    auto cp_K = [&](int st, int kt) {
        const int k0 = kt * KT;
#pragma unroll
        for (int r = 0; r < 8; r++) {
            int id = tid + r * 128;
            int row = id >> 4, c4 = (id & 15) * 4;
            cp16(&Ks[st * KT * STR + row * STR + c4], &Kb[(size_t)(k0 + row) * HDIM + c4]);
        }
        asm volatile("cp.async.commit_group;");
    };
    auto cp_V = [&](int kt) {
        const int k0 = kt * KT;
#pragma unroll
        for (int r = 0; r < 8; r++) {
            int id = tid + r * 128;
            int row = id >> 4, c4 = (id & 15) * 4;  // row = hd
            cp16(&Vs[row * STR + c4], &Vb[(size_t)row * TK + k0 + c4]);
        }
        asm volatile("cp.async.commit_group;");
    };

    cp_K(0, 0);
    asm volatile("cp.async.wait_group 0;");
    __syncthreads();

    float m_i[2][2], l_i[2][2], o[2][8][4];
#pragma unroll
    for (int mt = 0; mt < 2; mt++) {
#pragma unroll
        for (int hf = 0; hf < 2; hf++) { m_i[mt][hf] = -INFINITY; l_i[mt][hf] = 0.f; }
#pragma unroll
        for (int nf = 0; nf < 8; nf++)
#pragma unroll
            for (int c = 0; c < 4; c++) o[mt][nf][c] = 0.f;
    }

    const int NT = TK / KT;   // 32
    for (int kt = 0; kt < NT; kt++) {
        const int k0 = kt * KT;

        cp_V(kt);
        if (kt + 1 < NT) cp_K((kt + 1) & 1, kt + 1);
        if (kt + 1 < NT) asm volatile("cp.async.wait_group 2;");
        else             asm volatile("cp.async.wait_group 1;");
        __syncthreads();

        const float* Kst = &Ks[(kt & 1) * KT * STR];

        // S = Q @ K^T
        float s[2][8][4];
#pragma unroll
        for (int mt = 0; mt < 2; mt++)
#pragma unroll
            for (int nf = 0; nf < 8; nf++)
#pragma unroll
                for (int c = 0; c < 4; c++) s[mt][nf][c] = 0.f;

#pragma unroll
        for (int kk = 0; kk < 8; kk++) {
            unsigned af[2][4];
#pragma unroll
            for (int mt = 0; mt < 2; mt++) {
                const int row = warp * 32 + mt * 16 + lr;
                float2 a0 = *(const float2*)&Qs[row * STR + kk * 8 + 2 * lc];
                float2 a1 = *(const float2*)&Qs[(row + 8) * STR + kk * 8 + 2 * lc];
                af[mt][0] = __float_as_uint(a0.x);
                af[mt][1] = __float_as_uint(a1.x);
                af[mt][2] = __float_as_uint(a0.y);
                af[mt][3] = __float_as_uint(a1.y);
            }
#pragma unroll
            for (int nf = 0; nf < 8; nf++) {
                unsigned bf[2];
                float2 bv = *(const float2*)&Kst[(nf * 8 + lr) * STR + kk * 8 + 2 * lc];
                bf[0] = __float_as_uint(bv.x);
                bf[1] = __float_as_uint(bv.y);
                mma_tf32(s[0][nf], af[0], bf);
                mma_tf32(s[1][nf], af[1], bf);
            }
        }

        // masks + online softmax
        uchar2 kp[8];
#pragma unroll
        for (int nf = 0; nf < 8; nf++)
            kp[nf] = *(const uchar2*)&kpm[(size_t)b * TK + k0 + nf * 8 + 2 * lc];

#pragma unroll
        for (int mt = 0; mt < 2; mt++) {
#pragma unroll
            for (int hf = 0; hf < 2; hf++) {
                const int qg = q0 + warp * 32 + mt * 16 + lr + hf * 8;
                const float* mrow = &mask[(size_t)qg * TK + k0];
                float mx = -INFINITY;
#pragma unroll
                for (int nf = 0; nf < 8; nf++) {
                    float2 mv = *(const float2*)&mrow[nf * 8 + 2 * lc];
                    float v0 = s[mt][nf][hf * 2]     + mv.x;
                    float v1 = s[mt][nf][hf * 2 + 1] + mv.y;
                    if (kp[nf].x) v0 = -INFINITY;
                    if (kp[nf].y) v1 = -INFINITY;
                    s[mt][nf][hf * 2]     = v0;
                    s[mt][nf][hf * 2 + 1] = v1;
                    mx = fmaxf(mx, fmaxf(v0, v1));
                }
                mx = fmaxf(mx, __shfl_xor_sync(0xffffffffu, mx, 1));
                mx = fmaxf(mx, __shfl_xor_sync(0xffffffffu, mx, 2));
                float mnew = fmaxf(m_i[mt][hf], mx);
                float alpha, rs = 0.f;
                if (mnew == -INFINITY) {
                    alpha = 1.f;
#pragma unroll
                    for (int nf = 0; nf < 8; nf++) {
                        s[mt][nf][hf * 2] = 0.f;
                        s[mt][nf][hf * 2 + 1] = 0.f;
                    }
                } else {
                    alpha = (m_i[mt][hf] == -INFINITY) ? 0.f : __expf(m_i[mt][hf] - mnew);
#pragma unroll
                    for (int nf = 0; nf < 8; nf++) {
                        float p0 = __expf(s[mt][nf][hf * 2]     - mnew);
                        float p1 = __expf(s[mt][nf][hf * 2 + 1] - mnew);
                        s[mt][nf][hf * 2]     = p0;
                        s[mt][nf][hf * 2 + 1] = p1;
                        rs += p0 + p1;
                    }
                }
                rs += __shfl_xor_sync(0xffffffffu, rs, 1);
                rs += __shfl_xor_sync(0xffffffffu, rs, 2);
                l_i[mt][hf] = l_i[mt][hf] * alpha + rs;
                m_i[mt][hf] = mnew;
#pragma unroll
                for (int nf = 0; nf < 8; nf++) {
                    o[mt][nf][hf * 2]     *= alpha;
                    o[mt][nf][hf * 2 + 1] *= alpha;
                }
            }
        }

        // convert P to tf32 bits in-place
#pragma unroll
        for (int mt = 0; mt < 2; mt++)
#pragma unroll
            for (int nf = 0; nf < 8; nf++)
#pragma unroll
                for (int c = 0; c < 4; c++)
                    s[mt][nf][c] = __uint_as_float(f2tf(s[mt][nf][c]));

        // V ready
        if (kt + 1 < NT) asm volatile("cp.async.wait_group 1;");
        else             asm volatile("cp.async.wait_group 0;");
        __syncthreads();

        // O += P @ V : A-fragment via intra-quad shuffles, B from V^T smem
        const int srcA = (lane & ~3) | (lc >> 1);
        const int srcB = srcA + 2;
        const bool hi  = lc & 1;
#pragma unroll
        for (int kb = 0; kb < 8; kb++) {
            unsigned af[2][4];
#pragma unroll
            for (int mt = 0; mt < 2; mt++) {
                unsigned p0 = __float_as_uint(s[mt][kb][0]);
                unsigned p1 = __float_as_uint(s[mt][kb][1]);
                unsigned p2 = __float_as_uint(s[mt][kb][2]);
                unsigned p3 = __float_as_uint(s[mt][kb][3]);
                unsigned x0 = __shfl_sync(0xffffffffu, p0, srcA);
                unsigned x1 = __shfl_sync(0xffffffffu, p1, srcA);
                unsigned y0 = __shfl_sync(0xffffffffu, p2, srcA);
                unsigned y1 = __shfl_sync(0xffffffffu, p3, srcA);
                unsigned z0 = __shfl_sync(0xffffffffu, p0, srcB);
                unsigned z1 = __shfl_sync(0xffffffffu, p1, srcB);
                unsigned w0 = __shfl_sync(0xffffffffu, p2, srcB);
                unsigned w1 = __shfl_sync(0xffffffffu, p3, srcB);
                af[mt][0] = hi ? x1 : x0;
                af[mt][1] = hi ? y1 : y0;
                af[mt][2] = hi ? z1 : z0;
                af[mt][3] = hi ? w1 : w0;
            }
#pragma unroll
            for (int nf = 0; nf < 8; nf++) {
                unsigned bf[2];
                float2 bv = *(const float2*)&Vs[(nf * 8 + lr) * STR + kb * 8 + 2 * lc];
                bf[0] = __float_as_uint(bv.x);
                bf[1] = __float_as_uint(bv.y);
                mma_tf32(o[0][nf], af[0], bf);
                mma_tf32(o[1][nf], af[1], bf);
            }
        }
        __syncthreads();   // all reads done before next stage overwrites
    }

    // finalize: (b,t,dmodel), tf32 bits (consumed by final GEMM)
#pragma unroll
    for (int mt = 0; mt < 2; mt++)
#pragma unroll
        for (int hf = 0; hf < 2; hf++) {
            const float inv = (l_i[mt][hf] > 0.f) ? (1.f / l_i[mt][hf]) : 0.f;
            const int t = q0 + warp * 32 + mt * 16 + lr + hf * 8;
#pragma unroll
            for (int nf = 0; nf < 8; nf++) {
                float2 v;
                v.x = __uint_as_float(f2tf(o[mt][nf][hf * 2] * inv));
                v.y = __uint_as_float(f2tf(o[mt][nf][hf * 2 + 1] * inv));
                *(float2*)&O[((size_t)(b * TQ + t)) * DMODEL + h * HDIM + nf * 8 + 2 * lc] = v;
            }
        }
}

// ---------------- launch -------------------------------------------------------
extern "C" void kernel_launch(void* const* d_in, const int* in_sizes, int n_in,
                              void* d_out, int out_size)
{
    const float* x_q   = (const float*)d_in[0];
    const float* x_kv  = (const float*)d_in[1];
    const float* amask = (const float*)d_in[2];
    const unsigned char* kpm = (const unsigned char*)d_in[3];
    const float* Wq = (const float*)d_in[4];
    const float* Wk = (const float*)d_in[5];
    const float* Wv = (const float*)d_in[6];
    const float* Wo = (const float*)d_in[7];
    float* out = (float*)d_out;

    float *qP, *kP, *vP, *oP, *xqP, *xkvP, *wqP, *wkP, *wvP, *woP;
    cudaGetSymbolAddress((void**)&qP,  g_Q);
    cudaGetSymbolAddress((void**)&kP,  g_K);
    cudaGetSymbolAddress((void**)&vP,  g_V);
    cudaGetSymbolAddress((void**)&oP,  g_O);
    cudaGetSymbolAddress((void**)&xqP, g_Xq);
    cudaGetSymbolAddress((void**)&xkvP,g_Xkv);
    cudaGetSymbolAddress((void**)&wqP, g_Wq);
    cudaGetSymbolAddress((void**)&wkP, g_Wk);
    cudaGetSymbolAddress((void**)&wvP, g_Wv);
    cudaGetSymbolAddress((void**)&woP, g_Wo);

    // pre-convert inputs to tf32 bits (paired along k where needed)
    const int NX = MROWS * DMODEL;   // 8M
    const int NW = DMODEL * DMODEL;  // 1M
    cvt_pair_kernel <<<NX / 4 / 256, 256>>>(x_q,  xqP,  NX);
    cvt_pair_kernel <<<NX / 4 / 256, 256>>>(x_kv, xkvP, NX);
    cvt_pair_kernel <<<NW / 4 / 256, 256>>>(Wq, wqP, NW);
    cvt_pair_kernel <<<NW / 4 / 256, 256>>>(Wk, wkP, NW);
    cvt_pair_kernel <<<NW / 4 / 256, 256>>>(Wv, wvP, NW);
    cvt_plain_kernel<<<NW / 4 / 256, 256>>>(Wo, woP, NW);

    const int gemm_smem = 2 * (BM + BN) * SSTR * (int)sizeof(float);   // 81920
    cudaFuncSetAttribute(gemm_tf32<0,false>, cudaFuncAttributeMaxDynamicSharedMemorySize, gemm_smem);
    cudaFuncSetAttribute(gemm_tf32<1,true>,  cudaFuncAttributeMaxDynamicSharedMemorySize, gemm_smem);
    cudaFuncSetAttribute(gemm_tf32<2,true>,  cudaFuncAttributeMaxDynamicSharedMemorySize, gemm_smem);

    dim3 gblk(DMODEL / BN, MROWS / BM);   // (8, 64)
    gemm_tf32<1,true><<<gblk, 256, gemm_smem>>>(xqP,  wqP, qP, 0.125f);
    gemm_tf32<1,true><<<gblk, 256, gemm_smem>>>(xkvP, wkP, kP, 1.0f);
    gemm_tf32<2,true><<<gblk, 256, gemm_smem>>>(xkvP, wvP, vP, 1.0f);

    const int attn_smem = (AQ * STR + 2 * KT * STR + KT * STR) * (int)sizeof(float); // 92160
    cudaFuncSetAttribute(attn_tf32, cudaFuncAttributeMaxDynamicSharedMemorySize, attn_smem);
    dim3 ga(TQ / AQ, BATCH * NHEADS);     // (16, 64)
    attn_tf32<<<ga, 128, attn_smem>>>(qP, kP, vP, amask, kpm, oP);

    gemm_tf32<0,false><<<gblk, 256, gemm_smem>>>(oP, woP, out, 1.0f);
}

// round 6
// speedup vs baseline: 1.7541x; 1.7541x over previous
#include <cuda_runtime.h>
#include <cuda_fp16.h>
#include <math.h>

#define BATCH   4
#define TQ      2048
#define TK      2048
#define DMODEL  1024
#define NHEADS  16
#define HDIM    64
#define MROWS   (BATCH * TQ)   // 8192

// ---------------- scratch (__device__ globals; no allocation allowed) -------
// "interleaved" = within each 16-element k-block, pair j (elements 2j,2j+1)
// stored at slot (j<4 ? 2j : 2j-7), i.e. pairs for k and k+8 are adjacent ->
// every mma.sync fp16 fragment is a single LDS.64.
__device__ __half h_Q[MROWS * DMODEL];   // (b,h,t,hd-interleaved), prescaled 1/8
__device__ __half h_K[MROWS * DMODEL];   // (b,h,t,hd-interleaved)
__device__ __half h_V[MROWS * DMODEL];   // (b,h,hd,t-interleaved)  (V^T)
__device__ __half h_O[MROWS * DMODEL];   // (b,t,dmodel-interleaved)
__device__ __half h_Xq[MROWS * DMODEL];  // x_q  interleaved
__device__ __half h_Xkv[MROWS * DMODEL]; // x_kv interleaved
__device__ __half h_Wq[DMODEL * DMODEL];
__device__ __half h_Wk[DMODEL * DMODEL];
__device__ __half h_Wv[DMODEL * DMODEL];
__device__ __half h_Wo[DMODEL * DMODEL];

// ---------------- helpers ----------------------------------------------------
__device__ __forceinline__ void mma_f16(float* d, const unsigned* a, const unsigned* b) {
    asm volatile(
        "mma.sync.aligned.m16n8k16.row.col.f32.f16.f16.f32 "
        "{%0,%1,%2,%3}, {%4,%5,%6,%7}, {%8,%9}, {%0,%1,%2,%3};"
        : "+f"(d[0]), "+f"(d[1]), "+f"(d[2]), "+f"(d[3])
        : "r"(a[0]), "r"(a[1]), "r"(a[2]), "r"(a[3]), "r"(b[0]), "r"(b[1]));
}

__device__ __forceinline__ unsigned pack_h2(float lo, float hi) {
    __half2 h = __floats2half2_rn(lo, hi);
    return *(unsigned*)&h;
}

__device__ __forceinline__ void cp16(void* smem_dst, const void* gmem_src) {
    unsigned s = (unsigned)__cvta_generic_to_shared(smem_dst);
    asm volatile("cp.async.cg.shared.global [%0], [%1], 16;" :: "r"(s), "l"(gmem_src));
}

// interleave slot for pair j within a 16-block
__device__ __forceinline__ int islot(int j) { return (j < 4) ? 2 * j : 2 * j - 7; }

// ---------------- pre-convert: fp32 -> fp16, k-pair-interleaved ---------------
__global__ void cvt_h16_kernel(const float* __restrict__ src, __half* __restrict__ dst,
                               int n, float scale)
{
    int i8 = (blockIdx.x * blockDim.x + threadIdx.x) * 8;
    if (i8 >= n) return;
    float4 v0 = *(const float4*)&src[i8];
    float4 v1 = *(const float4*)&src[i8 + 4];
    int base2 = (i8 & ~15) >> 1;           // half2 index of 16-block start
    int hi = (i8 & 15) ? 1 : 0;            // pairs j=0..3 or j=4..7
    __half2* d = (__half2*)dst;
    d[base2 + 0 + hi] = __floats2half2_rn(v0.x * scale, v0.y * scale);
    d[base2 + 2 + hi] = __floats2half2_rn(v0.z * scale, v0.w * scale);
    d[base2 + 4 + hi] = __floats2half2_rn(v1.x * scale, v1.y * scale);
    d[base2 + 6 + hi] = __floats2half2_rn(v1.z * scale, v1.w * scale);
}

// ---------------- fp16 GEMM: C = A(M,K) @ W(N,K)^T ----------------------------
// 128x128x32 block, 256 threads, 8 warps of 64x32, cp.async double buffer.
// A and W are fp16 interleaved. MODE 0: fp32 row-major out.
// MODE 1: split-heads (b,h,t,hd-interleaved) fp16, *scale.  MODE 2: V^T fp16.
#define BM   128
#define BN   128
#define BKH  32     // k halves per stage
#define GST  48     // smem stride in halves (96B rows -> conflict-free LDS.64)

template <int MODE>
__global__ void __launch_bounds__(256, 2)
gemm_h16(const __half* __restrict__ A, const __half* __restrict__ W,
         void* __restrict__ Cv, float scale)
{
    extern __shared__ __half smh[];
    __half* As = smh;                      // [2][BM][GST]
    __half* Ws = smh + 2 * BM * GST;       // [2][BN][GST]

    const int tid  = threadIdx.x;
    const int lane = tid & 31;
    const int warp = tid >> 5;
    const int wm   = warp >> 2;
    const int wn   = warp & 3;
    const int bm   = blockIdx.y * BM;
    const int bn   = blockIdx.x * BN;
    const int lr   = lane >> 2;
    const int lc   = lane & 3;

    float acc[4][4][4];
#pragma unroll
    for (int i = 0; i < 4; i++)
#pragma unroll
        for (int j = 0; j < 4; j++)
#pragma unroll
            for (int c = 0; c < 4; c++) acc[i][j][c] = 0.f;

    const int NIT = DMODEL / BKH;  // 32

    auto load_stage = [&](int st, int k0) {
#pragma unroll
        for (int r = 0; r < 2; r++) {
            int id  = tid + r * 256;       // 512 ids: 128 rows x 4 chunks of 8 halves
            int m   = id >> 2;
            int c8  = (id & 3) * 8;
            cp16(&As[(st * BM + m) * GST + c8], &A[(size_t)(bm + m) * DMODEL + k0 + c8]);
            cp16(&Ws[(st * BN + m) * GST + c8], &W[(size_t)(bn + m) * DMODEL + k0 + c8]);
        }
        asm volatile("cp.async.commit_group;");
    };

    load_stage(0, 0);

    for (int it = 0; it < NIT; it++) {
        if (it + 1 < NIT) {
            load_stage((it + 1) & 1, (it + 1) * BKH);
            asm volatile("cp.async.wait_group 1;");
        } else {
            asm volatile("cp.async.wait_group 0;");
        }
        __syncthreads();
        const __half* Ab = &As[(it & 1) * BM * GST];
        const __half* Wb = &Ws[(it & 1) * BN * GST];

#pragma unroll
        for (int kk = 0; kk < 2; kk++) {   // two k16 blocks
            unsigned af[4][4], bf[4][2];
#pragma unroll
            for (int mf = 0; mf < 4; mf++) {
                const int row = wm * 64 + mf * 16 + lr;
                uint2 u0 = *(const uint2*)&Ab[row * GST + kk * 16 + 4 * lc];
                uint2 u1 = *(const uint2*)&Ab[(row + 8) * GST + kk * 16 + 4 * lc];
                af[mf][0] = u0.x; af[mf][1] = u1.x; af[mf][2] = u0.y; af[mf][3] = u1.y;
            }
#pragma unroll
            for (int nf = 0; nf < 4; nf++) {
                const int row = wn * 32 + nf * 8 + lr;
                uint2 u = *(const uint2*)&Wb[row * GST + kk * 16 + 4 * lc];
                bf[nf][0] = u.x; bf[nf][1] = u.y;
            }
#pragma unroll
            for (int mf = 0; mf < 4; mf++)
#pragma unroll
                for (int nf = 0; nf < 4; nf++)
                    mma_f16(acc[mf][nf], af[mf], bf[nf]);
        }
        __syncthreads();
    }

    // epilogue
#pragma unroll
    for (int mf = 0; mf < 4; mf++) {
#pragma unroll
        for (int half = 0; half < 2; half++) {
            const int m = bm + wm * 64 + mf * 16 + lr + half * 8;
#pragma unroll
            for (int nf = 0; nf < 4; nf++) {
                const int n = bn + wn * 32 + nf * 8 + 2 * lc;
                float c0 = acc[mf][nf][half * 2], c1 = acc[mf][nf][half * 2 + 1];
                if (MODE == 0) {
                    float* C = (float*)Cv;
                    *(float2*)&C[(size_t)m * DMODEL + n] = make_float2(c0, c1);
                } else if (MODE == 1) {
                    __half* C = (__half*)Cv;
                    const int b = m >> 11, t = m & 2047;
                    const int h = n >> 6;
                    const int hd = n & 63;
                    const int offd = (hd & ~15) + 2 * islot((hd & 15) >> 1);
                    __half2 hv = __floats2half2_rn(c0 * scale, c1 * scale);
                    *(__half2*)&C[(((size_t)(b * NHEADS + h) * TQ + t) << 6) + offd] = hv;
                } else {
                    // V^T: (b,h,hd,t-interleaved); m = t (key), n / n+1 = hd rows
                    __half* C = (__half*)Cv;
                    const int b = m >> 11, t = m & 2047;
                    const int h = n >> 6;
                    const int hd0 = n & 63;
                    const int col = (t & ~15) + 2 * islot((t & 15) >> 1) + (t & 1);
                    __half* base = &C[((size_t)(b * NHEADS + h) * HDIM) * (size_t)TK];
                    base[(size_t)hd0 * TK + col]       = __float2half_rn(c0);
                    base[(size_t)(hd0 + 1) * TK + col] = __float2half_rn(c1);
                }
            }
        }
    }
}

// ---------------- fused attention, fp16 mma ------------------------------------
// 64 q-rows, 4 warps (16 rows each); KT=64 keys; K double-buffered cp.async,
// V^T single-buffered overlapped. P converts to fragments in registers.
#define AQ   64
#define KT   64
#define ASTR 80   // halves; 160B rows -> conflict-free LDS.64

__global__ void __launch_bounds__(128, 3)
attn_h16(const __half* __restrict__ Q, const __half* __restrict__ K,
         const __half* __restrict__ V, const float* __restrict__ mask,
         const unsigned char* __restrict__ kpm, __half* __restrict__ O)
{
    extern __shared__ __half smh[];
    __half* Qs = smh;                      // 64 x 80
    __half* Ks = smh + AQ * ASTR;          // [2][64][80]
    __half* Vs = Ks + 2 * KT * ASTR;       // 64 x 80 (V^T: rows=hd, cols=t-interleaved)

    const int tid  = threadIdx.x;
    const int lane = tid & 31;
    const int warp = tid >> 5;
    const int lr   = lane >> 2;
    const int lc   = lane & 3;

    const int q0 = blockIdx.x * AQ;
    const int bh = blockIdx.y;
    const int b  = bh >> 4;
    const int h  = bh & 15;

    const __half* Qb = Q + (size_t)bh * TQ * HDIM;
    const __half* Kb = K + (size_t)bh * TK * HDIM;
    const __half* Vb = V + (size_t)bh * HDIM * TK;

    // stage Q (64 rows x 64 halves = 8 cp16/row)
#pragma unroll
    for (int r = 0; r < 4; r++) {
        int id = tid + r * 128;            // 512 ids: 64 rows x 8 chunks
        int row = id >> 3, c8 = (id & 7) * 8;
        cp16(&Qs[row * ASTR + c8], &Qb[(size_t)(q0 + row) * HDIM + c8]);
    }
    asm volatile("cp.async.commit_group;");

    auto cp_K = [&](int st, int kt) {
        const int k0 = kt * KT;
#pragma unroll
        for (int r = 0; r < 4; r++) {
            int id = tid + r * 128;
            int row = id >> 3, c8 = (id & 7) * 8;
            cp16(&Ks[st * KT * ASTR + row * ASTR + c8], &Kb[(size_t)(k0 + row) * HDIM + c8]);
        }
        asm volatile("cp.async.commit_group;");
    };
    auto cp_V = [&](int kt) {
        const int k0 = kt * KT;
#pragma unroll
        for (int r = 0; r < 4; r++) {
            int id = tid + r * 128;
            int row = id >> 3, c8 = (id & 7) * 8;   // row = hd
            cp16(&Vs[row * ASTR + c8], &Vb[(size_t)row * TK + k0 + c8]);
        }
        asm volatile("cp.async.commit_group;");
    };

    cp_K(0, 0);
    asm volatile("cp.async.wait_group 0;");
    __syncthreads();

    // hoist Q fragments (4 k16 blocks)
    unsigned qf[4][4];
#pragma unroll
    for (int kk = 0; kk < 4; kk++) {
        const int row = warp * 16 + lr;
        uint2 u0 = *(const uint2*)&Qs[row * ASTR + kk * 16 + 4 * lc];
        uint2 u1 = *(const uint2*)&Qs[(row + 8) * ASTR + kk * 16 + 4 * lc];
        qf[kk][0] = u0.x; qf[kk][1] = u1.x; qf[kk][2] = u0.y; qf[kk][3] = u1.y;
    }

    float m_i[2] = {-INFINITY, -INFINITY};
    float l_i[2] = {0.f, 0.f};
    float o[8][4];
#pragma unroll
    for (int nf = 0; nf < 8; nf++)
#pragma unroll
        for (int c = 0; c < 4; c++) o[nf][c] = 0.f;

    const int NT = TK / KT;   // 32
    for (int kt = 0; kt < NT; kt++) {
        const int k0 = kt * KT;

        cp_V(kt);
        if (kt + 1 < NT) cp_K((kt + 1) & 1, kt + 1);
        if (kt + 1 < NT) asm volatile("cp.async.wait_group 2;");
        else             asm volatile("cp.async.wait_group 1;");
        __syncthreads();

        const __half* Kst = &Ks[(kt & 1) * KT * ASTR];

        // S = Q @ K^T
        float s[8][4];
#pragma unroll
        for (int nf = 0; nf < 8; nf++)
#pragma unroll
            for (int c = 0; c < 4; c++) s[nf][c] = 0.f;

#pragma unroll
        for (int kk = 0; kk < 4; kk++) {
#pragma unroll
            for (int nf = 0; nf < 8; nf++) {
                unsigned bf[2];
                uint2 u = *(const uint2*)&Kst[(nf * 8 + lr) * ASTR + kk * 16 + 4 * lc];
                bf[0] = u.x; bf[1] = u.y;
                mma_f16(s[nf], qf[kk], bf);
            }
        }

        // masks + online softmax
        uchar2 kp[8];
#pragma unroll
        for (int nf = 0; nf < 8; nf++)
            kp[nf] = *(const uchar2*)&kpm[(size_t)b * TK + k0 + nf * 8 + 2 * lc];

#pragma unroll
        for (int hf = 0; hf < 2; hf++) {
            const int qg = q0 + warp * 16 + lr + hf * 8;
            const float* mrow = &mask[(size_t)qg * TK + k0];
            float mx = -INFINITY;
#pragma unroll
            for (int nf = 0; nf < 8; nf++) {
                float2 mv = *(const float2*)&mrow[nf * 8 + 2 * lc];
                float v0 = s[nf][hf * 2]     + mv.x;
                float v1 = s[nf][hf * 2 + 1] + mv.y;
                if (kp[nf].x) v0 = -INFINITY;
                if (kp[nf].y) v1 = -INFINITY;
                s[nf][hf * 2]     = v0;
                s[nf][hf * 2 + 1] = v1;
                mx = fmaxf(mx, fmaxf(v0, v1));
            }
            mx = fmaxf(mx, __shfl_xor_sync(0xffffffffu, mx, 1));
            mx = fmaxf(mx, __shfl_xor_sync(0xffffffffu, mx, 2));
            float mnew = fmaxf(m_i[hf], mx);
            float alpha, rs = 0.f;
            if (mnew == -INFINITY) {
                alpha = 1.f;
#pragma unroll
                for (int nf = 0; nf < 8; nf++) {
                    s[nf][hf * 2] = 0.f;
                    s[nf][hf * 2 + 1] = 0.f;
                }
            } else {
                alpha = (m_i[hf] == -INFINITY) ? 0.f : __expf(m_i[hf] - mnew);
#pragma unroll
                for (int nf = 0; nf < 8; nf++) {
                    float p0 = __expf(s[nf][hf * 2]     - mnew);
                    float p1 = __expf(s[nf][hf * 2 + 1] - mnew);
                    s[nf][hf * 2]     = p0;
                    s[nf][hf * 2 + 1] = p1;
                    rs += p0 + p1;
                }
            }
            rs += __shfl_xor_sync(0xffffffffu, rs, 1);
            rs += __shfl_xor_sync(0xffffffffu, rs, 2);
            l_i[hf] = l_i[hf] * alpha + rs;
            m_i[hf] = mnew;
#pragma unroll
            for (int nf = 0; nf < 8; nf++) {
                o[nf][hf * 2]     *= alpha;
                o[nf][hf * 2 + 1] *= alpha;
            }
        }

        // V ready
        if (kt + 1 < NT) asm volatile("cp.async.wait_group 1;");
        else             asm volatile("cp.async.wait_group 0;");
        __syncthreads();

        // O += P @ V : P fragment built in registers from s (fp32 -> fp16x2)
#pragma unroll
        for (int kb = 0; kb < 4; kb++) {
            unsigned af[4];
            af[0] = pack_h2(s[2 * kb][0],     s[2 * kb][1]);
            af[1] = pack_h2(s[2 * kb][2],     s[2 * kb][3]);
            af[2] = pack_h2(s[2 * kb + 1][0], s[2 * kb + 1][1]);
            af[3] = pack_h2(s[2 * kb + 1][2], s[2 * kb + 1][3]);
#pragma unroll
            for (int nf = 0; nf < 8; nf++) {
                unsigned bf[2];
                uint2 u = *(const uint2*)&Vs[(nf * 8 + lr) * ASTR + kb * 16 + 4 * lc];
                bf[0] = u.x; bf[1] = u.y;
                mma_f16(o[nf], af, bf);
            }
        }
        __syncthreads();   // PV reads done before next cp_V overwrites Vs
    }

    // finalize: (b,t,dmodel-interleaved) fp16 (consumed by final GEMM)
#pragma unroll
    for (int hf = 0; hf < 2; hf++) {
        const float inv = (l_i[hf] > 0.f) ? (1.f / l_i[hf]) : 0.f;
        const int t = q0 + warp * 16 + lr + hf * 8;
#pragma unroll
        for (int nf = 0; nf < 8; nf++) {
            const int n = h * HDIM + nf * 8 + 2 * lc;
            const int offd = (n & ~15) + 2 * islot((n & 15) >> 1);
            __half2 hv = __floats2half2_rn(o[nf][hf * 2] * inv, o[nf][hf * 2 + 1] * inv);
            *(__half2*)&O[((size_t)(b * TQ + t)) * DMODEL + offd] = hv;
        }
    }
}

// ---------------- launch --------------------------------------------------------
extern "C" void kernel_launch(void* const* d_in, const int* in_sizes, int n_in,
                              void* d_out, int out_size)
{
    const float* x_q   = (const float*)d_in[0];
    const float* x_kv  = (const float*)d_in[1];
    const float* amask = (const float*)d_in[2];
    const unsigned char* kpm = (const unsigned char*)d_in[3];
    const float* Wq = (const float*)d_in[4];
    const float* Wk = (const float*)d_in[5];
    const float* Wv = (const float*)d_in[6];
    const float* Wo = (const float*)d_in[7];
    float* out = (float*)d_out;

    __half *qP, *kP, *vP, *oP, *xqP, *xkvP, *wqP, *wkP, *wvP, *woP;
    cudaGetSymbolAddress((void**)&qP,  h_Q);
    cudaGetSymbolAddress((void**)&kP,  h_K);
    cudaGetSymbolAddress((void**)&vP,  h_V);
    cudaGetSymbolAddress((void**)&oP,  h_O);
    cudaGetSymbolAddress((void**)&xqP, h_Xq);
    cudaGetSymbolAddress((void**)&xkvP,h_Xkv);
    cudaGetSymbolAddress((void**)&wqP, h_Wq);
    cudaGetSymbolAddress((void**)&wkP, h_Wk);
    cudaGetSymbolAddress((void**)&wvP, h_Wv);
    cudaGetSymbolAddress((void**)&woP, h_Wo);

    const int NX = MROWS * DMODEL;   // 8M
    const int NW = DMODEL * DMODEL;  // 1M
    cvt_h16_kernel<<<NX / 8 / 256, 256>>>(x_q,  xqP,  NX, 1.0f);
    cvt_h16_kernel<<<NX / 8 / 256, 256>>>(x_kv, xkvP, NX, 1.0f);
    cvt_h16_kernel<<<NW / 8 / 256, 256>>>(Wq, wqP, NW, 1.0f);
    cvt_h16_kernel<<<NW / 8 / 256, 256>>>(Wk, wkP, NW, 1.0f);
    cvt_h16_kernel<<<NW / 8 / 256, 256>>>(Wv, wvP, NW, 1.0f);
    cvt_h16_kernel<<<NW / 8 / 256, 256>>>(Wo, woP, NW, 1.0f);

    const int gemm_smem = 2 * (BM + BN) * GST * (int)sizeof(__half);   // 49152
    cudaFuncSetAttribute(gemm_h16<0>, cudaFuncAttributeMaxDynamicSharedMemorySize, gemm_smem);
    cudaFuncSetAttribute(gemm_h16<1>, cudaFuncAttributeMaxDynamicSharedMemorySize, gemm_smem);
    cudaFuncSetAttribute(gemm_h16<2>, cudaFuncAttributeMaxDynamicSharedMemorySize, gemm_smem);

    dim3 gblk(DMODEL / BN, MROWS / BM);   // (8, 64)
    gemm_h16<1><<<gblk, 256, gemm_smem>>>(xqP,  wqP, qP, 0.125f);
    gemm_h16<1><<<gblk, 256, gemm_smem>>>(xkvP, wkP, kP, 1.0f);
    gemm_h16<2><<<gblk, 256, gemm_smem>>>(xkvP, wvP, vP, 1.0f);

    const int attn_smem = 4 * KT * ASTR * (int)sizeof(__half);   // 40960
    cudaFuncSetAttribute(attn_h16, cudaFuncAttributeMaxDynamicSharedMemorySize, attn_smem);
    dim3 ga(TQ / AQ, BATCH * NHEADS);     // (32, 64)
    attn_h16<<<ga, 128, attn_smem>>>(qP, kP, vP, amask, kpm, oP);

    gemm_h16<0><<<gblk, 256, gemm_smem>>>(oP, woP, out, 1.0f);
}

// round 8
// speedup vs baseline: 1.7820x; 1.0159x over previous
#include <cuda_runtime.h>
#include <cuda_fp16.h>
#include <math.h>

#define BATCH   4
#define TQ      2048
#define TK      2048
#define DMODEL  1024
#define NHEADS  16
#define HDIM    64
#define MROWS   (BATCH * TQ)   // 8192

// ---------------- scratch (__device__ globals; no allocation allowed) -------
// "interleaved" = within each 16-element k-block, pair j at slot (j<4?2j:2j-7)
// so every mma.sync fp16 fragment is a single LDS.64.
__device__ __half h_Q[MROWS * DMODEL];   // (b,h,t,hd-interleaved), prescaled 1/8
__device__ __half h_K[MROWS * DMODEL];   // (b,h,t,hd-interleaved)
__device__ __half h_V[MROWS * DMODEL];   // (b,h,hd,t-interleaved)  (V^T)
__device__ __half h_O[MROWS * DMODEL];   // (b,t,dmodel-interleaved)
__device__ __half h_Xq[MROWS * DMODEL];  // x_q  interleaved
__device__ __half h_Xkv[MROWS * DMODEL]; // x_kv interleaved
__device__ __half h_Wq[DMODEL * DMODEL];
__device__ __half h_Wk[DMODEL * DMODEL];
__device__ __half h_Wv[DMODEL * DMODEL];
__device__ __half h_Wo[DMODEL * DMODEL];
__device__ __half h_Mask[TQ * TK];       // additive mask, fp16

// ---------------- helpers ----------------------------------------------------
__device__ __forceinline__ void mma_f16(float* d, const unsigned* a, const unsigned* b) {
    asm volatile(
        "mma.sync.aligned.m16n8k16.row.col.f32.f16.f16.f32 "
        "{%0,%1,%2,%3}, {%4,%5,%6,%7}, {%8,%9}, {%0,%1,%2,%3};"
        : "+f"(d[0]), "+f"(d[1]), "+f"(d[2]), "+f"(d[3])
        : "r"(a[0]), "r"(a[1]), "r"(a[2]), "r"(a[3]), "r"(b[0]), "r"(b[1]));
}

__device__ __forceinline__ unsigned pack_h2(float lo, float hi) {
    __half2 h = __floats2half2_rn(lo, hi);
    return *(unsigned*)&h;
}

__device__ __forceinline__ void cp16(void* smem_dst, const void* gmem_src) {
    unsigned s = (unsigned)__cvta_generic_to_shared(smem_dst);
    asm volatile("cp.async.cg.shared.global [%0], [%1], 16;" :: "r"(s), "l"(gmem_src));
}

__device__ __forceinline__ int islot(int j) { return (j < 4) ? 2 * j : 2 * j - 7; }

// ---------------- pre-convert: fp32 -> fp16, k-pair-interleaved ---------------
__global__ void cvt_h16_kernel(const float* __restrict__ src, __half* __restrict__ dst,
                               int n, float scale)
{
    int i8 = (blockIdx.x * blockDim.x + threadIdx.x) * 8;
    if (i8 >= n) return;
    float4 v0 = *(const float4*)&src[i8];
    float4 v1 = *(const float4*)&src[i8 + 4];
    int base2 = (i8 & ~15) >> 1;
    int hi = (i8 & 15) ? 1 : 0;
    __half2* d = (__half2*)dst;
    d[base2 + 0 + hi] = __floats2half2_rn(v0.x * scale, v0.y * scale);
    d[base2 + 2 + hi] = __floats2half2_rn(v0.z * scale, v0.w * scale);
    d[base2 + 4 + hi] = __floats2half2_rn(v1.x * scale, v1.y * scale);
    d[base2 + 6 + hi] = __floats2half2_rn(v1.z * scale, v1.w * scale);
}

// plain fp32 -> fp16 (for the additive mask)
__global__ void cvt_mask_kernel(const float* __restrict__ src, __half* __restrict__ dst, int n) {
    int i8 = (blockIdx.x * blockDim.x + threadIdx.x) * 8;
    if (i8 >= n) return;
    float4 v0 = *(const float4*)&src[i8];
    float4 v1 = *(const float4*)&src[i8 + 4];
    __half2 h[4];
    h[0] = __floats2half2_rn(v0.x, v0.y);
    h[1] = __floats2half2_rn(v0.z, v0.w);
    h[2] = __floats2half2_rn(v1.x, v1.y);
    h[3] = __floats2half2_rn(v1.z, v1.w);
    *(uint4*)&dst[i8] = *(uint4*)h;
}

// ---------------- fp16 GEMM: C = A(M,K) @ W(N,K)^T ----------------------------
// 128x128x64 block, 256 threads, 8 warps of 64x32, cp.async double buffer.
// MODE 0: fp32 row-major out. MODE 1: split-heads interleaved fp16 (*scale).
// MODE 2: V^T (b,h,hd,t-interleaved) fp16.
#define BM   128
#define BN   128
#define BKH  64     // k halves per stage
#define GST  80     // smem stride in halves; 40 words = 8 mod 32 -> conflict-free LDS.64

template <int MODE>
__global__ void __launch_bounds__(256, 2)
gemm_h16(const __half* __restrict__ A, const __half* __restrict__ W,
         void* __restrict__ Cv, float scale)
{
    extern __shared__ __half smh[];
    __half* As = smh;                      // [2][BM][GST]
    __half* Ws = smh + 2 * BM * GST;       // [2][BN][GST]

    const int tid  = threadIdx.x;
    const int lane = tid & 31;
    const int warp = tid >> 5;
    const int wm   = warp >> 2;
    const int wn   = warp & 3;
    const int bm   = blockIdx.y * BM;
    const int bn   = blockIdx.x * BN;
    const int lr   = lane >> 2;
    const int lc   = lane & 3;

    float acc[4][4][4];
#pragma unroll
    for (int i = 0; i < 4; i++)
#pragma unroll
        for (int j = 0; j < 4; j++)
#pragma unroll
            for (int c = 0; c < 4; c++) acc[i][j][c] = 0.f;

    const int NIT = DMODEL / BKH;  // 16

    auto load_stage = [&](int st, int k0) {
#pragma unroll
        for (int r = 0; r < 4; r++) {
            int id  = tid + r * 256;       // 1024 ids: 128 rows x 8 chunks of 8 halves
            int m   = id >> 3;
            int c8  = (id & 7) * 8;
            cp16(&As[(st * BM + m) * GST + c8], &A[(size_t)(bm + m) * DMODEL + k0 + c8]);
        }
#pragma unroll
        for (int r = 0; r < 4; r++) {
            int id  = tid + r * 256;
            int m   = id >> 3;
            int c8  = (id & 7) * 8;
            cp16(&Ws[(st * BN + m) * GST + c8], &W[(size_t)(bn + m) * DMODEL + k0 + c8]);
        }
        asm volatile("cp.async.commit_group;");
    };

    load_stage(0, 0);

    for (int it = 0; it < NIT; it++) {
        if (it + 1 < NIT) {
            load_stage((it + 1) & 1, (it + 1) * BKH);
            asm volatile("cp.async.wait_group 1;");
        } else {
            asm volatile("cp.async.wait_group 0;");
        }
        __syncthreads();
        const __half* Ab = &As[(it & 1) * BM * GST];
        const __half* Wb = &Ws[(it & 1) * BN * GST];

#pragma unroll
        for (int kk = 0; kk < 4; kk++) {   // four k16 blocks per stage
            unsigned af[4][4], bf[4][2];
#pragma unroll
            for (int mf = 0; mf < 4; mf++) {
                const int row = wm * 64 + mf * 16 + lr;
                uint2 u0 = *(const uint2*)&Ab[row * GST + kk * 16 + 4 * lc];
                uint2 u1 = *(const uint2*)&Ab[(row + 8) * GST + kk * 16 + 4 * lc];
                af[mf][0] = u0.x; af[mf][1] = u1.x; af[mf][2] = u0.y; af[mf][3] = u1.y;
            }
#pragma unroll
            for (int nf = 0; nf < 4; nf++) {
                const int row = wn * 32 + nf * 8 + lr;
                uint2 u = *(const uint2*)&Wb[row * GST + kk * 16 + 4 * lc];
                bf[nf][0] = u.x; bf[nf][1] = u.y;
            }
#pragma unroll
            for (int mf = 0; mf < 4; mf++)
#pragma unroll
                for (int nf = 0; nf < 4; nf++)
                    mma_f16(acc[mf][nf], af[mf], bf[nf]);
        }
        __syncthreads();
    }

    // epilogue
#pragma unroll
    for (int mf = 0; mf < 4; mf++) {
#pragma unroll
        for (int half = 0; half < 2; half++) {
            const int m = bm + wm * 64 + mf * 16 + lr + half * 8;
#pragma unroll
            for (int nf = 0; nf < 4; nf++) {
                const int n = bn + wn * 32 + nf * 8 + 2 * lc;
                float c0 = acc[mf][nf][half * 2], c1 = acc[mf][nf][half * 2 + 1];
                if (MODE == 0) {
                    float* C = (float*)Cv;
                    *(float2*)&C[(size_t)m * DMODEL + n] = make_float2(c0, c1);
                } else if (MODE == 1) {
                    __half* C = (__half*)Cv;
                    const int b = m >> 11, t = m & 2047;
                    const int h = n >> 6;
                    const int hd = n & 63;
                    const int offd = (hd & ~15) + 2 * islot((hd & 15) >> 1);
                    __half2 hv = __floats2half2_rn(c0 * scale, c1 * scale);
                    *(__half2*)&C[(((size_t)(b * NHEADS + h) * TQ + t) << 6) + offd] = hv;
                } else {
                    __half* C = (__half*)Cv;
                    const int b = m >> 11, t = m & 2047;
                    const int h = n >> 6;
                    const int hd0 = n & 63;
                    const int col = (t & ~15) + 2 * islot((t & 15) >> 1) + (t & 1);
                    __half* base = &C[((size_t)(b * NHEADS + h) * HDIM) * (size_t)TK];
                    base[(size_t)hd0 * TK + col]       = __float2half_rn(c0);
                    base[(size_t)(hd0 + 1) * TK + col] = __float2half_rn(c1);
                }
            }
        }
    }
}

// ---------------- fused attention, fp16 mma ------------------------------------
// 64 q-rows, 4 warps (16 rows each); KT=64 keys; K double-buffered cp.async,
// V^T single-buffered overlapped. P converts to fragments in registers.
// Additive mask read as fp16.
#define AQ   64
#define KT   64
#define ASTR 80   // halves; 40 words = 8 mod 32 -> conflict-free LDS.64

__global__ void __launch_bounds__(128, 3)
attn_h16(const __half* __restrict__ Q, const __half* __restrict__ K,
         const __half* __restrict__ V, const __half* __restrict__ mask,
         const unsigned char* __restrict__ kpm, __half* __restrict__ O)
{
    extern __shared__ __half smh[];
    __half* Qs = smh;                      // 64 x 80
    __half* Ks = smh + AQ * ASTR;          // [2][64][80]
    __half* Vs = Ks + 2 * KT * ASTR;       // 64 x 80 (V^T)

    const int tid  = threadIdx.x;
    const int lane = tid & 31;
    const int warp = tid >> 5;
    const int lr   = lane >> 2;
    const int lc   = lane & 3;

    const int q0 = blockIdx.x * AQ;
    const int bh = blockIdx.y;
    const int b  = bh >> 4;
    const int h  = bh & 15;

    const __half* Qb = Q + (size_t)bh * TQ * HDIM;
    const __half* Kb = K + (size_t)bh * TK * HDIM;
    const __half* Vb = V + (size_t)bh * HDIM * TK;

#pragma unroll
    for (int r = 0; r < 4; r++) {
        int id = tid + r * 128;
        int row = id >> 3, c8 = (id & 7) * 8;
        cp16(&Qs[row * ASTR + c8], &Qb[(size_t)(q0 + row) * HDIM + c8]);
    }
    asm volatile("cp.async.commit_group;");

    auto cp_K = [&](int st, int kt) {
        const int k0 = kt * KT;
#pragma unroll
        for (int r = 0; r < 4; r++) {
            int id = tid + r * 128;
            int row = id >> 3, c8 = (id & 7) * 8;
            cp16(&Ks[st * KT * ASTR + row * ASTR + c8], &Kb[(size_t)(k0 + row) * HDIM + c8]);
        }
        asm volatile("cp.async.commit_group;");
    };
    auto cp_V = [&](int kt) {
        const int k0 = kt * KT;
#pragma unroll
        for (int r = 0; r < 4; r++) {
            int id = tid + r * 128;
            int row = id >> 3, c8 = (id & 7) * 8;
            cp16(&Vs[row * ASTR + c8], &Vb[(size_t)row * TK + k0 + c8]);
        }
        asm volatile("cp.async.commit_group;");
    };

    cp_K(0, 0);
    asm volatile("cp.async.wait_group 0;");
    __syncthreads();

    unsigned qf[4][4];
#pragma unroll
    for (int kk = 0; kk < 4; kk++) {
        const int row = warp * 16 + lr;
        uint2 u0 = *(const uint2*)&Qs[row * ASTR + kk * 16 + 4 * lc];
        uint2 u1 = *(const uint2*)&Qs[(row + 8) * ASTR + kk * 16 + 4 * lc];
        qf[kk][0] = u0.x; qf[kk][1] = u1.x; qf[kk][2] = u0.y; qf[kk][3] = u1.y;
    }

    float m_i[2] = {-INFINITY, -INFINITY};
    float l_i[2] = {0.f, 0.f};
    float o[8][4];
#pragma unroll
    for (int nf = 0; nf < 8; nf++)
#pragma unroll
        for (int c = 0; c < 4; c++) o[nf][c] = 0.f;

    const int NT = TK / KT;   // 32
    for (int kt = 0; kt < NT; kt++) {
        const int k0 = kt * KT;

        cp_V(kt);
        if (kt + 1 < NT) cp_K((kt + 1) & 1, kt + 1);
        if (kt + 1 < NT) asm volatile("cp.async.wait_group 2;");
        else             asm volatile("cp.async.wait_group 1;");
        __syncthreads();

        const __half* Kst = &Ks[(kt & 1) * KT * ASTR];

        float s[8][4];
#pragma unroll
        for (int nf = 0; nf < 8; nf++)
#pragma unroll
            for (int c = 0; c < 4; c++) s[nf][c] = 0.f;

#pragma unroll
        for (int kk = 0; kk < 4; kk++) {
#pragma unroll
            for (int nf = 0; nf < 8; nf++) {
                unsigned bf[2];
                uint2 u = *(const uint2*)&Kst[(nf * 8 + lr) * ASTR + kk * 16 + 4 * lc];
                bf[0] = u.x; bf[1] = u.y;
                mma_f16(s[nf], qf[kk], bf);
            }
        }

        uchar2 kp[8];
#pragma unroll
        for (int nf = 0; nf < 8; nf++)
            kp[nf] = *(const uchar2*)&kpm[(size_t)b * TK + k0 + nf * 8 + 2 * lc];

#pragma unroll
        for (int hf = 0; hf < 2; hf++) {
            const int qg = q0 + warp * 16 + lr + hf * 8;
            const __half* mrow = &mask[(size_t)qg * TK + k0];
            float mx = -INFINITY;
#pragma unroll
            for (int nf = 0; nf < 8; nf++) {
                float2 mv = __half22float2(*(const __half2*)&mrow[nf * 8 + 2 * lc]);
                float v0 = s[nf][hf * 2]     + mv.x;
                float v1 = s[nf][hf * 2 + 1] + mv.y;
                if (kp[nf].x) v0 = -INFINITY;
                if (kp[nf].y) v1 = -INFINITY;
                s[nf][hf * 2]     = v0;
                s[nf][hf * 2 + 1] = v1;
                mx = fmaxf(mx, fmaxf(v0, v1));
            }
            mx = fmaxf(mx, __shfl_xor_sync(0xffffffffu, mx, 1));
            mx = fmaxf(mx, __shfl_xor_sync(0xffffffffu, mx, 2));
            float mnew = fmaxf(m_i[hf], mx);
            float alpha, rs = 0.f;
            if (mnew == -INFINITY) {
                alpha = 1.f;
#pragma unroll
                for (int nf = 0; nf < 8; nf++) {
                    s[nf][hf * 2] = 0.f;
                    s[nf][hf * 2 + 1] = 0.f;
                }
            } else {
                alpha = (m_i[hf] == -INFINITY) ? 0.f : __expf(m_i[hf] - mnew);
#pragma unroll
                for (int nf = 0; nf < 8; nf++) {
                    float p0 = __expf(s[nf][hf * 2]     - mnew);
                    float p1 = __expf(s[nf][hf * 2 + 1] - mnew);
                    s[nf][hf * 2]     = p0;
                    s[nf][hf * 2 + 1] = p1;
                    rs += p0 + p1;
                }
            }
            rs += __shfl_xor_sync(0xffffffffu, rs, 1);
            rs += __shfl_xor_sync(0xffffffffu, rs, 2);
            l_i[hf] = l_i[hf] * alpha + rs;
            m_i[hf] = mnew;
#pragma unroll
            for (int nf = 0; nf < 8; nf++) {
                o[nf][hf * 2]     *= alpha;
                o[nf][hf * 2 + 1] *= alpha;
            }
        }

        if (kt + 1 < NT) asm volatile("cp.async.wait_group 1;");
        else             asm volatile("cp.async.wait_group 0;");
        __syncthreads();

#pragma unroll
        for (int kb = 0; kb < 4; kb++) {
            unsigned af[4];
            af[0] = pack_h2(s[2 * kb][0],     s[2 * kb][1]);
            af[1] = pack_h2(s[2 * kb][2],     s[2 * kb][3]);
            af[2] = pack_h2(s[2 * kb + 1][0], s[2 * kb + 1][1]);
            af[3] = pack_h2(s[2 * kb + 1][2], s[2 * kb + 1][3]);
#pragma unroll
            for (int nf = 0; nf < 8; nf++) {
                unsigned bf[2];
                uint2 u = *(const uint2*)&Vs[(nf * 8 + lr) * ASTR + kb * 16 + 4 * lc];
                bf[0] = u.x; bf[1] = u.y;
                mma_f16(o[nf], af, bf);
            }
        }
        __syncthreads();
    }

    // finalize: (b,t,dmodel-interleaved) fp16 (consumed by final GEMM)
#pragma unroll
    for (int hf = 0; hf < 2; hf++) {
        const float inv = (l_i[hf] > 0.f) ? (1.f / l_i[hf]) : 0.f;
        const int t = q0 + warp * 16 + lr + hf * 8;
#pragma unroll
        for (int nf = 0; nf < 8; nf++) {
            const int n = h * HDIM + nf * 8 + 2 * lc;
            const int offd = (n & ~15) + 2 * islot((n & 15) >> 1);
            __half2 hv = __floats2half2_rn(o[nf][hf * 2] * inv, o[nf][hf * 2 + 1] * inv);
            *(__half2*)&O[((size_t)(b * TQ + t)) * DMODEL + offd] = hv;
        }
    }
}

// ---------------- launch --------------------------------------------------------
extern "C" void kernel_launch(void* const* d_in, const int* in_sizes, int n_in,
                              void* d_out, int out_size)
{
    const float* x_q   = (const float*)d_in[0];
    const float* x_kv  = (const float*)d_in[1];
    const float* amask = (const float*)d_in[2];
    const unsigned char* kpm = (const unsigned char*)d_in[3];
    const float* Wq = (const float*)d_in[4];
    const float* Wk = (const float*)d_in[5];
    const float* Wv = (const float*)d_in[6];
    const float* Wo = (const float*)d_in[7];
    float* out = (float*)d_out;

    __half *qP, *kP, *vP, *oP, *xqP, *xkvP, *wqP, *wkP, *wvP, *woP, *mP;
    cudaGetSymbolAddress((void**)&qP,  h_Q);
    cudaGetSymbolAddress((void**)&kP,  h_K);
    cudaGetSymbolAddress((void**)&vP,  h_V);
    cudaGetSymbolAddress((void**)&oP,  h_O);
    cudaGetSymbolAddress((void**)&xqP, h_Xq);
    cudaGetSymbolAddress((void**)&xkvP,h_Xkv);
    cudaGetSymbolAddress((void**)&wqP, h_Wq);
    cudaGetSymbolAddress((void**)&wkP, h_Wk);
    cudaGetSymbolAddress((void**)&wvP, h_Wv);
    cudaGetSymbolAddress((void**)&woP, h_Wo);
    cudaGetSymbolAddress((void**)&mP,  h_Mask);

    const int NX = MROWS * DMODEL;   // 8M
    const int NW = DMODEL * DMODEL;  // 1M
    const int NM = TQ * TK;          // 4M
    cvt_h16_kernel<<<NX / 8 / 256, 256>>>(x_q,  xqP,  NX, 1.0f);
    cvt_h16_kernel<<<NX / 8 / 256, 256>>>(x_kv, xkvP, NX, 1.0f);
    cvt_h16_kernel<<<NW / 8 / 256, 256>>>(Wq, wqP, NW, 1.0f);
    cvt_h16_kernel<<<NW / 8 / 256, 256>>>(Wk, wkP, NW, 1.0f);
    cvt_h16_kernel<<<NW / 8 / 256, 256>>>(Wv, wvP, NW, 1.0f);
    cvt_h16_kernel<<<NW / 8 / 256, 256>>>(Wo, woP, NW, 1.0f);
    cvt_mask_kernel<<<NM / 8 / 256, 256>>>(amask, mP, NM);

    const int gemm_smem = 2 * (BM + BN) * GST * (int)sizeof(__half);   // 81920
    cudaFuncSetAttribute(gemm_h16<0>, cudaFuncAttributeMaxDynamicSharedMemorySize, gemm_smem);
    cudaFuncSetAttribute(gemm_h16<1>, cudaFuncAttributeMaxDynamicSharedMemorySize, gemm_smem);
    cudaFuncSetAttribute(gemm_h16<2>, cudaFuncAttributeMaxDynamicSharedMemorySize, gemm_smem);

    dim3 gblk(DMODEL / BN, MROWS / BM);   // (8, 64)
    gemm_h16<1><<<gblk, 256, gemm_smem>>>(xqP,  wqP, qP, 0.125f);
    gemm_h16<1><<<gblk, 256, gemm_smem>>>(xkvP, wkP, kP, 1.0f);
    gemm_h16<2><<<gblk, 256, gemm_smem>>>(xkvP, wvP, vP, 1.0f);

    const int attn_smem = 4 * KT * ASTR * (int)sizeof(__half);   // 40960
    cudaFuncSetAttribute(attn_h16, cudaFuncAttributeMaxDynamicSharedMemorySize, attn_smem);
    dim3 ga(TQ / AQ, BATCH * NHEADS);     // (32, 64)
    attn_h16<<<ga, 128, attn_smem>>>(qP, kP, vP, mP, kpm, oP);

    gemm_h16<0><<<gblk, 256, gemm_smem>>>(oP, woP, out, 1.0f);
}